// round 15
// baseline (speedup 1.0000x reference)
#include <cuda_runtime.h>
#include <math.h>
#include <stdint.h>

#define NUM_CLASSES 1000000
#define DIMK 64
#define BATCHN 4096
#define NS 1024
#define TC 256         // cols per block (one tile)
#define RPB 64         // batch rows per block (8 warps x 8 rows)
#define NSPLIT 4       // column splits (NS / TC)

typedef unsigned long long ull;

// Scratch (device globals: allocation-free per harness rules)
__device__ float g_ST[DIMK * NS];      // gathered sampled weights, d-major [64][1024]
__device__ float g_slq[NS];            // samp_log_q
__device__ float g_pm[NSPLIT * BATCHN];// partial max per (split,row)
__device__ float g_ps[NSPLIT * BATCHN];// partial expsum per (split,row)
__device__ float g_tp[NSPLIT * BATCHN];// partial true-dot per (split,row)

// ---------------------------------------------------------------------------
// PROVEN reference-log (R8, rel_err 5.7e-8): XLA:CPU GenerateVF32Log —
// Cephes constants, q1/q2 split ln2, Estrin 3-chain, ALL mul/adds unfused,
// old-Eigen tail order. DO NOT MODIFY.
// ---------------------------------------------------------------------------
__device__ __forceinline__ float xla_logf(float xx) {
    uint32_t ib = __float_as_uint(xx);
    float e = __fadd_rn((float)((int)(ib >> 23) - 0x7f), 1.0f);
    float x = __uint_as_float((ib & 0x007fffffu) | 0x3f000000u);  // [0.5, 1)
    bool mask = x < 0.707106781186547524f;
    float tmp = mask ? x : 0.0f;
    x = __fadd_rn(x, -1.0f);
    e = __fadd_rn(e, mask ? -1.0f : 0.0f);
    x = __fadd_rn(x, tmp);

    float x2 = __fmul_rn(x, x);
    float x3 = __fmul_rn(x2, x);

    float y  = __fadd_rn(__fmul_rn(7.0376836292E-2f, x), -1.1514610310E-1f);
    float y1 = __fadd_rn(__fmul_rn(-1.2420140846E-1f, x), 1.4249322787E-1f);
    float y2 = __fadd_rn(__fmul_rn(2.0000714765E-1f, x), -2.4999993993E-1f);
    y  = __fadd_rn(__fmul_rn(y, x), 1.1676998740E-1f);
    y1 = __fadd_rn(__fmul_rn(y1, x), -1.6668057665E-1f);
    y2 = __fadd_rn(__fmul_rn(y2, x), 3.3333331174E-1f);
    y  = __fadd_rn(__fmul_rn(y, x3), y1);
    y  = __fadd_rn(__fmul_rn(y, x3), y2);
    y  = __fmul_rn(y, x3);

    float t1 = __fmul_rn(e, -2.12194440e-4f);
    float t2 = __fmul_rn(x2, 0.5f);
    y = __fadd_rn(y, t1);
    x = __fadd_rn(x, -t2);
    float t3 = __fmul_rn(e, 0.693359375f);
    x = __fadd_rn(x, y);
    x = __fadd_rn(x, t3);
    return x;
}

__device__ __forceinline__ float log_q_of(int c) {
    float cf = (float)c;
    float l2 = xla_logf(__fadd_rn(cf, 2.0f));
    float l1 = xla_logf(__fadd_rn(cf, 1.0f));
    float lnc = xla_logf(1000001.0f);
    float p = __fdiv_rn(__fadd_rn(l2, -l1), lnc);
    float np = __fmul_rn(1024.0f, p);
    return xla_logf(np);
}

// ---- packed f32x2 helpers (sm_100+) ----
__device__ __forceinline__ ull pk2(float v) {
    ull r; asm("mov.b64 %0, {%1, %1};" : "=l"(r) : "f"(v)); return r;
}
__device__ __forceinline__ ull fma2(ull a, ull b, ull c) {
    ull d; asm("fma.rn.f32x2 %0, %1, %2, %3;" : "=l"(d) : "l"(a), "l"(b), "l"(c)); return d;
}
__device__ __forceinline__ float2 up2(ull v) {
    float2 f; asm("mov.b64 {%0, %1}, %2;" : "=f"(f.x), "=f"(f.y) : "l"(v)); return f;
}

// K1: pure sampled-column gather + sampled log-q's. 256 blocks.
__global__ void __launch_bounds__(256) prep_kernel(
    const float* __restrict__ item,
    const int*   __restrict__ sid)
{
    int idx = blockIdx.x * 256 + (int)threadIdx.x;   // 0 .. 65535
    int j = idx & 1023;
    int c = sid[j];
    g_ST[idx] = item[(size_t)(idx >> 10) * NUM_CLASSES + (size_t)c];
    if (idx < NS) g_slq[idx] = log_q_of(c);
}

// K2: GEMM + masked partial softmax + hidden true-dot slice.
// Block = 64 rows x 256 cols; grid (64, 4) = 256 blocks; smem ~83KB ->
// 2 blocks/SM -> 296 capacity >= 256 -> ALL blocks resident, no wave tail.
// __launch_bounds__(256,2) -> 128-reg cap -> NO SPILLS (the R12-R14 killer).
// Micro-tile 8 rows x 8 cols (32 ull acc). Per-logit d-order identical ->
// logits bit-identical to prior passing rounds.
__global__ void __launch_bounds__(256, 2) fused_kernel(
    const float* __restrict__ item,
    const float* __restrict__ user,
    const int*   __restrict__ labels,
    const int*   __restrict__ sid)
{
    extern __shared__ float Ss[];        // [64][TC] = 64KB (dynamic)
    __shared__ float Us[DIMK][RPB];      // A tile [d][row], 16KB
    __shared__ float slq_s[TC];
    __shared__ int   sid_s[TC];
    __shared__ int   lab_s[RPB];

    int tid = (int)threadIdx.x;
    int b0 = blockIdx.x * RPB;
    int j0 = blockIdx.y * TC;

    // Stage B tile [64][256] (4096 float4, 16 per thread)
    for (int u = tid; u < DIMK * (TC / 4); u += 256) {
        int d = u >> 6, x = (u & 63) << 2;
        *(float4*)&Ss[d * TC + x] = *(const float4*)&g_ST[d * NS + j0 + x];
    }
    // Stage A tile [64][64]
    for (int t = tid; t < DIMK * RPB; t += 256) {
        int d = t >> 6, r = t & 63;
        Us[d][r] = user[(size_t)d * BATCHN + b0 + r];
    }
    { slq_s[tid] = g_slq[j0 + tid]; sid_s[tid] = sid[j0 + tid]; }
    if (tid < RPB) lab_s[tid] = labels[b0 + tid];
    __syncthreads();

    // True-dot slice: this split covers d in [16*y, 16*y+16). 4 loads/thread,
    // hoisted LDG hidden under the FMA mainloop.
    int trow = tid >> 2;                       // 0..63
    int tq = tid & 3;                          // 0..3
    int td0 = blockIdx.y * 16 + 4 * tq;
    int tlab = lab_s[trow];
    float tv0 = item[(size_t)td0 * NUM_CLASSES + tlab];
    float tv1 = item[(size_t)(td0 + 1) * NUM_CLASSES + tlab];
    float tv2 = item[(size_t)(td0 + 2) * NUM_CLASSES + tlab];
    float tv3 = item[(size_t)(td0 + 3) * NUM_CLASSES + tlab];

    int wid = tid >> 5;            // 0..7
    int l = tid & 31;              // lane
    int r0 = wid * 8;              // 8 rows per warp

    ull acc[8][4];
    #pragma unroll
    for (int i = 0; i < 8; i++)
        #pragma unroll
        for (int p = 0; p < 4; p++) acc[i][p] = 0;

    #pragma unroll 4
    for (int d = 0; d < DIMK; d++) {
        const float* sr = &Ss[d * TC];
        ull bp0 = *(const ull*)&sr[2 * l];
        ull bp1 = *(const ull*)&sr[2 * l + 64];
        ull bp2 = *(const ull*)&sr[2 * l + 128];
        ull bp3 = *(const ull*)&sr[2 * l + 192];
        float4 av0 = *(const float4*)&Us[d][r0];      // broadcast
        float4 av1 = *(const float4*)&Us[d][r0 + 4];  // broadcast
        ull a;
        a = pk2(av0.x); acc[0][0] = fma2(a, bp0, acc[0][0]); acc[0][1] = fma2(a, bp1, acc[0][1]);
                        acc[0][2] = fma2(a, bp2, acc[0][2]); acc[0][3] = fma2(a, bp3, acc[0][3]);
        a = pk2(av0.y); acc[1][0] = fma2(a, bp0, acc[1][0]); acc[1][1] = fma2(a, bp1, acc[1][1]);
                        acc[1][2] = fma2(a, bp2, acc[1][2]); acc[1][3] = fma2(a, bp3, acc[1][3]);
        a = pk2(av0.z); acc[2][0] = fma2(a, bp0, acc[2][0]); acc[2][1] = fma2(a, bp1, acc[2][1]);
                        acc[2][2] = fma2(a, bp2, acc[2][2]); acc[2][3] = fma2(a, bp3, acc[2][3]);
        a = pk2(av0.w); acc[3][0] = fma2(a, bp0, acc[3][0]); acc[3][1] = fma2(a, bp1, acc[3][1]);
                        acc[3][2] = fma2(a, bp2, acc[3][2]); acc[3][3] = fma2(a, bp3, acc[3][3]);
        a = pk2(av1.x); acc[4][0] = fma2(a, bp0, acc[4][0]); acc[4][1] = fma2(a, bp1, acc[4][1]);
                        acc[4][2] = fma2(a, bp2, acc[4][2]); acc[4][3] = fma2(a, bp3, acc[4][3]);
        a = pk2(av1.y); acc[5][0] = fma2(a, bp0, acc[5][0]); acc[5][1] = fma2(a, bp1, acc[5][1]);
                        acc[5][2] = fma2(a, bp2, acc[5][2]); acc[5][3] = fma2(a, bp3, acc[5][3]);
        a = pk2(av1.z); acc[6][0] = fma2(a, bp0, acc[6][0]); acc[6][1] = fma2(a, bp1, acc[6][1]);
                        acc[6][2] = fma2(a, bp2, acc[6][2]); acc[6][3] = fma2(a, bp3, acc[6][3]);
        a = pk2(av1.w); acc[7][0] = fma2(a, bp0, acc[7][0]); acc[7][1] = fma2(a, bp1, acc[7][1]);
                        acc[7][2] = fma2(a, bp2, acc[7][2]); acc[7][3] = fma2(a, bp3, acc[7][3]);
    }

    // True-dot partial: 4 products/thread, quad-reduce, one write per row
    {
        float tp = tv0 * Us[td0][trow]     + tv1 * Us[td0 + 1][trow]
                 + tv2 * Us[td0 + 2][trow] + tv3 * Us[td0 + 3][trow];
        tp += __shfl_xor_sync(0xffffffffu, tp, 1);
        tp += __shfl_xor_sync(0xffffffffu, tp, 2);
        if (tq == 0) g_tp[blockIdx.y * BATCHN + b0 + trow] = tp;
    }

    // Epilogue: logits, mask, per-lane max/sum, lane-combine, write partials
    float q0 = slq_s[2 * l],       q1 = slq_s[2 * l + 1];
    float q2 = slq_s[2 * l + 64],  q3 = slq_s[2 * l + 65];
    float q4 = slq_s[2 * l + 128], q5 = slq_s[2 * l + 129];
    float q6 = slq_s[2 * l + 192], q7 = slq_s[2 * l + 193];
    int i0 = sid_s[2 * l],       i1 = sid_s[2 * l + 1];
    int i2 = sid_s[2 * l + 64],  i3 = sid_s[2 * l + 65];
    int i4 = sid_s[2 * l + 128], i5 = sid_s[2 * l + 129];
    int i6 = sid_s[2 * l + 192], i7 = sid_s[2 * l + 193];

    #pragma unroll
    for (int i = 0; i < 8; i++) {
        int lab = lab_s[r0 + i];
        float2 v0 = up2(acc[i][0]);
        float2 v1 = up2(acc[i][1]);
        float2 v2 = up2(acc[i][2]);
        float2 v3 = up2(acc[i][3]);
        float w0 = v0.x - q0 - (i0 == lab ? 1000000000.0f : 0.0f);
        float w1 = v0.y - q1 - (i1 == lab ? 1000000000.0f : 0.0f);
        float w2 = v1.x - q2 - (i2 == lab ? 1000000000.0f : 0.0f);
        float w3 = v1.y - q3 - (i3 == lab ? 1000000000.0f : 0.0f);
        float w4 = v2.x - q4 - (i4 == lab ? 1000000000.0f : 0.0f);
        float w5 = v2.y - q5 - (i5 == lab ? 1000000000.0f : 0.0f);
        float w6 = v3.x - q6 - (i6 == lab ? 1000000000.0f : 0.0f);
        float w7 = v3.y - q7 - (i7 == lab ? 1000000000.0f : 0.0f);
        float m = fmaxf(fmaxf(fmaxf(w0, w1), fmaxf(w2, w3)),
                        fmaxf(fmaxf(w4, w5), fmaxf(w6, w7)));
        float s = __expf(w0 - m) + __expf(w1 - m) + __expf(w2 - m) + __expf(w3 - m)
                + __expf(w4 - m) + __expf(w5 - m) + __expf(w6 - m) + __expf(w7 - m);
        #pragma unroll
        for (int o = 16; o; o >>= 1) {
            float om = __shfl_xor_sync(0xffffffffu, m, o);
            float os = __shfl_xor_sync(0xffffffffu, s, o);
            float mn = fmaxf(m, om);
            s = s * __expf(m - mn) + os * __expf(om - mn);
            m = mn;
        }
        if (l == 0) {
            int b = b0 + r0 + i;
            g_pm[blockIdx.y * BATCHN + b] = m;
            g_ps[blockIdx.y * BATCHN + b] = s;
        }
    }
}

// K3: merge partials + true logit + label log-q -> loss. One thread per row.
__global__ void __launch_bounds__(256) merge_kernel(
    const int* __restrict__ labels,
    float*     __restrict__ out)
{
    int b = blockIdx.x * 256 + (int)threadIdx.x;

    float td = 0.0f;
    #pragma unroll
    for (int sp = 0; sp < NSPLIT; sp++) td += g_tp[sp * BATCHN + b];
    float tl = td - log_q_of(labels[b]);

    float m = g_pm[b], s = g_ps[b];
    #pragma unroll
    for (int sp = 1; sp < NSPLIT; sp++) {
        float om = g_pm[sp * BATCHN + b];
        float os = g_ps[sp * BATCHN + b];
        float mn = fmaxf(m, om);
        s = s * __expf(m - mn) + os * __expf(om - mn);
        m = mn;
    }
    float mn = fmaxf(m, tl);
    float st = s * __expf(m - mn) + __expf(tl - mn);
    out[b] = mn + xla_logf(st) - tl;
}

extern "C" void kernel_launch(void* const* d_in, const int* in_sizes, int n_in,
                              void* d_out, int out_size)
{
    const float* item = (const float*)d_in[0];   // [64, 1000000]
    const float* user = (const float*)d_in[1];   // [64, 4096]
    const int*   lab  = (const int*)  d_in[2];   // [4096, 1]
    const int*   sid  = (const int*)  d_in[3];   // [1024]
    float*       out  = (float*)d_out;           // [4096, 1]

    cudaFuncSetAttribute(fused_kernel,
                         cudaFuncAttributeMaxDynamicSharedMemorySize, DIMK * TC * 4);

    prep_kernel<<<256, 256>>>(item, sid);
    fused_kernel<<<dim3(BATCHN / RPB, NSPLIT), 256, DIMK * TC * 4>>>(item, user, lab, sid);
    merge_kernel<<<BATCHN / 256, 256>>>(lab, out);
}

// round 17
// speedup vs baseline: 1.0696x; 1.0696x over previous
#include <cuda_runtime.h>
#include <math.h>
#include <stdint.h>

#define NUM_CLASSES 1000000
#define DIMK 64
#define BATCHN 4096
#define NS 1024
#define TC 256         // cols per block (one tile)
#define RPB 64         // batch rows per block (8 warps x 8 rows)
#define NSPLIT 4       // column splits (NS / TC)

typedef unsigned long long ull;

// Scratch (device globals: allocation-free per harness rules)
__device__ float g_ST[DIMK * NS];      // gathered sampled weights, d-major [64][1024]
__device__ float g_slq[NS];            // samp_log_q
__device__ float g_pm[NSPLIT * BATCHN];// partial max per (split,row)
__device__ float g_ps[NSPLIT * BATCHN];// partial expsum per (split,row)
__device__ float g_tp[NSPLIT * BATCHN];// partial true-dot per (split,row)
__device__ int   g_cnt[BATCHN / RPB];  // arrival counters (reset by last block)

// ---------------------------------------------------------------------------
// PROVEN reference-log (R8, rel_err 5.7e-8): XLA:CPU GenerateVF32Log —
// Cephes constants, q1/q2 split ln2, Estrin 3-chain, ALL mul/adds unfused,
// old-Eigen tail order. DO NOT MODIFY.
// ---------------------------------------------------------------------------
__device__ __forceinline__ float xla_logf(float xx) {
    uint32_t ib = __float_as_uint(xx);
    float e = __fadd_rn((float)((int)(ib >> 23) - 0x7f), 1.0f);
    float x = __uint_as_float((ib & 0x007fffffu) | 0x3f000000u);  // [0.5, 1)
    bool mask = x < 0.707106781186547524f;
    float tmp = mask ? x : 0.0f;
    x = __fadd_rn(x, -1.0f);
    e = __fadd_rn(e, mask ? -1.0f : 0.0f);
    x = __fadd_rn(x, tmp);

    float x2 = __fmul_rn(x, x);
    float x3 = __fmul_rn(x2, x);

    float y  = __fadd_rn(__fmul_rn(7.0376836292E-2f, x), -1.1514610310E-1f);
    float y1 = __fadd_rn(__fmul_rn(-1.2420140846E-1f, x), 1.4249322787E-1f);
    float y2 = __fadd_rn(__fmul_rn(2.0000714765E-1f, x), -2.4999993993E-1f);
    y  = __fadd_rn(__fmul_rn(y, x), 1.1676998740E-1f);
    y1 = __fadd_rn(__fmul_rn(y1, x), -1.6668057665E-1f);
    y2 = __fadd_rn(__fmul_rn(y2, x), 3.3333331174E-1f);
    y  = __fadd_rn(__fmul_rn(y, x3), y1);
    y  = __fadd_rn(__fmul_rn(y, x3), y2);
    y  = __fmul_rn(y, x3);

    float t1 = __fmul_rn(e, -2.12194440e-4f);
    float t2 = __fmul_rn(x2, 0.5f);
    y = __fadd_rn(y, t1);
    x = __fadd_rn(x, -t2);
    float t3 = __fmul_rn(e, 0.693359375f);
    x = __fadd_rn(x, y);
    x = __fadd_rn(x, t3);
    return x;
}

__device__ __forceinline__ float log_q_of(int c) {
    float cf = (float)c;
    float l2 = xla_logf(__fadd_rn(cf, 2.0f));
    float l1 = xla_logf(__fadd_rn(cf, 1.0f));
    float lnc = xla_logf(1000001.0f);
    float p = __fdiv_rn(__fadd_rn(l2, -l1), lnc);
    float np = __fmul_rn(1024.0f, p);
    return xla_logf(np);
}

// ---- packed f32x2 helpers (sm_100+) ----
__device__ __forceinline__ ull pk2(float v) {
    ull r; asm("mov.b64 %0, {%1, %1};" : "=l"(r) : "f"(v)); return r;
}
__device__ __forceinline__ ull fma2(ull a, ull b, ull c) {
    ull d; asm("fma.rn.f32x2 %0, %1, %2, %3;" : "=l"(d) : "l"(a), "l"(b), "l"(c)); return d;
}
__device__ __forceinline__ float2 up2(ull v) {
    float2 f; asm("mov.b64 {%0, %1}, %2;" : "=f"(f.x), "=f"(f.y) : "l"(v)); return f;
}

// K1: pure sampled-column gather + sampled log-q's. 256 blocks.
__global__ void __launch_bounds__(256) prep_kernel(
    const float* __restrict__ item,
    const int*   __restrict__ sid)
{
    int idx = blockIdx.x * 256 + (int)threadIdx.x;   // 0 .. 65535
    int j = idx & 1023;
    int c = sid[j];
    g_ST[idx] = item[(size_t)(idx >> 10) * NUM_CLASSES + (size_t)c];
    if (idx < NS) g_slq[idx] = log_q_of(c);
}

// K2: GEMM + masked partial softmax + hidden true-dot + LAST-BLOCK merge.
// Block = 64 rows x 256 cols; grid (64, 4) = 256 blocks; 2 blocks/SM, single
// wave. __launch_bounds__(256,2): 128-reg cap, no spills. The 4th block to
// finish a row-group merges all 4 splits (fixed order => deterministic) and
// writes the loss, replacing the separate merge kernel.
__global__ void __launch_bounds__(256, 2) fused_kernel(
    const float* __restrict__ item,
    const float* __restrict__ user,
    const int*   __restrict__ labels,
    const int*   __restrict__ sid,
    float*       __restrict__ out)
{
    extern __shared__ float Ss[];        // [64][TC] = 64KB (dynamic)
    __shared__ float Us[DIMK][RPB];      // A tile [d][row], 16KB
    __shared__ float slq_s[TC];
    __shared__ int   sid_s[TC];
    __shared__ int   lab_s[RPB];
    __shared__ int   arrive_s;

    int tid = (int)threadIdx.x;
    int b0 = blockIdx.x * RPB;
    int j0 = blockIdx.y * TC;

    // Stage B tile [64][256] (4096 float4, 16 per thread)
    for (int u = tid; u < DIMK * (TC / 4); u += 256) {
        int d = u >> 6, x = (u & 63) << 2;
        *(float4*)&Ss[d * TC + x] = *(const float4*)&g_ST[d * NS + j0 + x];
    }
    // Stage A tile [64][64]
    for (int t = tid; t < DIMK * RPB; t += 256) {
        int d = t >> 6, r = t & 63;
        Us[d][r] = user[(size_t)d * BATCHN + b0 + r];
    }
    { slq_s[tid] = g_slq[j0 + tid]; sid_s[tid] = sid[j0 + tid]; }
    if (tid < RPB) lab_s[tid] = labels[b0 + tid];
    __syncthreads();

    // True-dot slice: this split covers d in [16*y, 16*y+16). 4 loads/thread,
    // hoisted LDG hidden under the FMA mainloop.
    int trow = tid >> 2;                       // 0..63
    int tq = tid & 3;                          // 0..3
    int td0 = blockIdx.y * 16 + 4 * tq;
    int tlab = lab_s[trow];
    float tv0 = item[(size_t)td0 * NUM_CLASSES + tlab];
    float tv1 = item[(size_t)(td0 + 1) * NUM_CLASSES + tlab];
    float tv2 = item[(size_t)(td0 + 2) * NUM_CLASSES + tlab];
    float tv3 = item[(size_t)(td0 + 3) * NUM_CLASSES + tlab];

    int wid = tid >> 5;            // 0..7
    int l = tid & 31;              // lane
    int r0 = wid * 8;              // 8 rows per warp

    ull acc[8][4];
    #pragma unroll
    for (int i = 0; i < 8; i++)
        #pragma unroll
        for (int p = 0; p < 4; p++) acc[i][p] = 0;

    #pragma unroll 4
    for (int d = 0; d < DIMK; d++) {
        const float* sr = &Ss[d * TC];
        ull bp0 = *(const ull*)&sr[2 * l];
        ull bp1 = *(const ull*)&sr[2 * l + 64];
        ull bp2 = *(const ull*)&sr[2 * l + 128];
        ull bp3 = *(const ull*)&sr[2 * l + 192];
        float4 av0 = *(const float4*)&Us[d][r0];      // broadcast
        float4 av1 = *(const float4*)&Us[d][r0 + 4];  // broadcast
        ull a;
        a = pk2(av0.x); acc[0][0] = fma2(a, bp0, acc[0][0]); acc[0][1] = fma2(a, bp1, acc[0][1]);
                        acc[0][2] = fma2(a, bp2, acc[0][2]); acc[0][3] = fma2(a, bp3, acc[0][3]);
        a = pk2(av0.y); acc[1][0] = fma2(a, bp0, acc[1][0]); acc[1][1] = fma2(a, bp1, acc[1][1]);
                        acc[1][2] = fma2(a, bp2, acc[1][2]); acc[1][3] = fma2(a, bp3, acc[1][3]);
        a = pk2(av0.z); acc[2][0] = fma2(a, bp0, acc[2][0]); acc[2][1] = fma2(a, bp1, acc[2][1]);
                        acc[2][2] = fma2(a, bp2, acc[2][2]); acc[2][3] = fma2(a, bp3, acc[2][3]);
        a = pk2(av0.w); acc[3][0] = fma2(a, bp0, acc[3][0]); acc[3][1] = fma2(a, bp1, acc[3][1]);
                        acc[3][2] = fma2(a, bp2, acc[3][2]); acc[3][3] = fma2(a, bp3, acc[3][3]);
        a = pk2(av1.x); acc[4][0] = fma2(a, bp0, acc[4][0]); acc[4][1] = fma2(a, bp1, acc[4][1]);
                        acc[4][2] = fma2(a, bp2, acc[4][2]); acc[4][3] = fma2(a, bp3, acc[4][3]);
        a = pk2(av1.y); acc[5][0] = fma2(a, bp0, acc[5][0]); acc[5][1] = fma2(a, bp1, acc[5][1]);
                        acc[5][2] = fma2(a, bp2, acc[5][2]); acc[5][3] = fma2(a, bp3, acc[5][3]);
        a = pk2(av1.z); acc[6][0] = fma2(a, bp0, acc[6][0]); acc[6][1] = fma2(a, bp1, acc[6][1]);
                        acc[6][2] = fma2(a, bp2, acc[6][2]); acc[6][3] = fma2(a, bp3, acc[6][3]);
        a = pk2(av1.w); acc[7][0] = fma2(a, bp0, acc[7][0]); acc[7][1] = fma2(a, bp1, acc[7][1]);
                        acc[7][2] = fma2(a, bp2, acc[7][2]); acc[7][3] = fma2(a, bp3, acc[7][3]);
    }

    // True-dot partial: 4 products/thread, quad-reduce, one write per row
    {
        float tp = tv0 * Us[td0][trow]     + tv1 * Us[td0 + 1][trow]
                 + tv2 * Us[td0 + 2][trow] + tv3 * Us[td0 + 3][trow];
        tp += __shfl_xor_sync(0xffffffffu, tp, 1);
        tp += __shfl_xor_sync(0xffffffffu, tp, 2);
        if (tq == 0) g_tp[blockIdx.y * BATCHN + b0 + trow] = tp;
    }

    // Epilogue: logits, mask, per-lane max/sum, lane-combine, write partials
    float q0 = slq_s[2 * l],       q1 = slq_s[2 * l + 1];
    float q2 = slq_s[2 * l + 64],  q3 = slq_s[2 * l + 65];
    float q4 = slq_s[2 * l + 128], q5 = slq_s[2 * l + 129];
    float q6 = slq_s[2 * l + 192], q7 = slq_s[2 * l + 193];
    int i0 = sid_s[2 * l],       i1 = sid_s[2 * l + 1];
    int i2 = sid_s[2 * l + 64],  i3 = sid_s[2 * l + 65];
    int i4 = sid_s[2 * l + 128], i5 = sid_s[2 * l + 129];
    int i6 = sid_s[2 * l + 192], i7 = sid_s[2 * l + 193];

    #pragma unroll
    for (int i = 0; i < 8; i++) {
        int lab = lab_s[r0 + i];
        float2 v0 = up2(acc[i][0]);
        float2 v1 = up2(acc[i][1]);
        float2 v2 = up2(acc[i][2]);
        float2 v3 = up2(acc[i][3]);
        float w0 = v0.x - q0 - (i0 == lab ? 1000000000.0f : 0.0f);
        float w1 = v0.y - q1 - (i1 == lab ? 1000000000.0f : 0.0f);
        float w2 = v1.x - q2 - (i2 == lab ? 1000000000.0f : 0.0f);
        float w3 = v1.y - q3 - (i3 == lab ? 1000000000.0f : 0.0f);
        float w4 = v2.x - q4 - (i4 == lab ? 1000000000.0f : 0.0f);
        float w5 = v2.y - q5 - (i5 == lab ? 1000000000.0f : 0.0f);
        float w6 = v3.x - q6 - (i6 == lab ? 1000000000.0f : 0.0f);
        float w7 = v3.y - q7 - (i7 == lab ? 1000000000.0f : 0.0f);
        float m = fmaxf(fmaxf(fmaxf(w0, w1), fmaxf(w2, w3)),
                        fmaxf(fmaxf(w4, w5), fmaxf(w6, w7)));
        float s = __expf(w0 - m) + __expf(w1 - m) + __expf(w2 - m) + __expf(w3 - m)
                + __expf(w4 - m) + __expf(w5 - m) + __expf(w6 - m) + __expf(w7 - m);
        #pragma unroll
        for (int o = 16; o; o >>= 1) {
            float om = __shfl_xor_sync(0xffffffffu, m, o);
            float os = __shfl_xor_sync(0xffffffffu, s, o);
            float mn = fmaxf(m, om);
            s = s * __expf(m - mn) + os * __expf(om - mn);
            m = mn;
        }
        if (l == 0) {
            int b = b0 + r0 + i;
            g_pm[blockIdx.y * BATCHN + b] = m;
            g_ps[blockIdx.y * BATCHN + b] = s;
        }
    }

    // ---- last-block merge (deterministic: fixed split order) ----
    __syncthreads();               // all partial writes of this block issued
    if (tid == 0) {
        __threadfence();           // make them visible chip-wide (release)
        arrive_s = atomicAdd(&g_cnt[blockIdx.x], 1);
    }
    __syncthreads();
    if (arrive_s == NSPLIT - 1) {
        __threadfence();           // acquire side
        if (tid < RPB) {
            int b = b0 + tid;
            volatile float* vpm = g_pm;
            volatile float* vps = g_ps;
            volatile float* vtp = g_tp;
            float td = 0.0f;
            #pragma unroll
            for (int sp = 0; sp < NSPLIT; sp++) td += vtp[sp * BATCHN + b];
            float tl = td - log_q_of(lab_s[tid]);

            float m = vpm[b], s = vps[b];
            #pragma unroll
            for (int sp = 1; sp < NSPLIT; sp++) {
                float om = vpm[sp * BATCHN + b];
                float os = vps[sp * BATCHN + b];
                float mn = fmaxf(m, om);
                s = s * __expf(m - mn) + os * __expf(om - mn);
                m = mn;
            }
            float mn = fmaxf(m, tl);
            float st = s * __expf(m - mn) + __expf(tl - mn);
            out[b] = mn + xla_logf(st) - tl;
        }
        if (tid == 0) g_cnt[blockIdx.x] = 0;   // reset for next graph replay
    }
}

extern "C" void kernel_launch(void* const* d_in, const int* in_sizes, int n_in,
                              void* d_out, int out_size)
{
    const float* item = (const float*)d_in[0];   // [64, 1000000]
    const float* user = (const float*)d_in[1];   // [64, 4096]
    const int*   lab  = (const int*)  d_in[2];   // [4096, 1]
    const int*   sid  = (const int*)  d_in[3];   // [1024]
    float*       out  = (float*)d_out;           // [4096, 1]

    cudaFuncSetAttribute(fused_kernel,
                         cudaFuncAttributeMaxDynamicSharedMemorySize, DIMK * TC * 4);

    prep_kernel<<<256, 256>>>(item, sid);
    fused_kernel<<<dim3(BATCHN / RPB, NSPLIT), 256, DIMK * TC * 4>>>(item, user, lab, sid, out);
}